// round 2
// baseline (speedup 1.0000x reference)
#include <cuda_runtime.h>
#include <cuda_bf16.h>
#include <cstdint>

// GCN sparse aggregation: out[r,:] += vals[e] * embeds[cols[e],:]
// N_NODES=100000, N_EDGES=1600000, D=64, fp32.
//
// Round 2: replace the 410MB RED atomic stream with a gather-by-destination
// pass. Build per-node linked lists with atomicExch (one pass, no sort/scan),
// packing {next, col, val} into a single 16B int4 so the aggregate chase costs
// one broadcast wavefront per edge. Each node is handled by a 16-lane group
// (one float4 of the D=64 row per lane), accumulating in registers and doing a
// single coalesced float4 store per lane.

#define D_FEAT 64
#define N_NODES_MAX 100000
#define N_EDGES_MAX 1600000

// Device-global scratch (static — no runtime allocation).
__device__ int4 g_packed[N_EDGES_MAX];   // {next, col, val_as_int, pad}
__device__ int  g_head[N_NODES_MAX];

__global__ void init_kernel(float4* __restrict__ out4, int n4, int n_nodes) {
    int i = blockIdx.x * blockDim.x + threadIdx.x;
    int s = gridDim.x * blockDim.x;
    for (int j = i; j < n4; j += s)
        out4[j] = make_float4(0.f, 0.f, 0.f, 0.f);
    for (int j = i; j < n_nodes; j += s)
        g_head[j] = -1;
}

__global__ void __launch_bounds__(256) build_kernel(
    const int*   __restrict__ rows,
    const int*   __restrict__ cols,
    const float* __restrict__ vals,
    int n_edges)
{
    int e = blockIdx.x * blockDim.x + threadIdx.x;
    if (e >= n_edges) return;
    int r = rows[e];
    int c = cols[e];
    float v = vals[e];
    int old = atomicExch(&g_head[r], e);
    g_packed[e] = make_int4(old, c, __float_as_int(v), 0);
}

__global__ void __launch_bounds__(256) aggregate_kernel(
    const float4* __restrict__ embeds4,   // [N_NODES, 16] float4
    float4*       __restrict__ out4,      // [N_NODES, 16] float4
    int n_nodes)
{
    int t = blockIdx.x * blockDim.x + threadIdx.x;
    int node = t >> 4;
    int lane = t & 15;
    if (node >= n_nodes) return;

    float4 acc = make_float4(0.f, 0.f, 0.f, 0.f);
    int e = g_head[node];   // broadcast load across the 16-lane group
    while (e >= 0) {
        int4 p = __ldg(&g_packed[e]);             // 16B broadcast: next|col|val
        float v = __int_as_float(p.z);
        float4 x = __ldg(&embeds4[(size_t)p.y * (D_FEAT / 4) + lane]);
        acc.x += v * x.x;
        acc.y += v * x.y;
        acc.z += v * x.z;
        acc.w += v * x.w;
        e = p.x;
    }
    out4[(size_t)node * (D_FEAT / 4) + lane] = acc;
}

extern "C" void kernel_launch(void* const* d_in, const int* in_sizes, int n_in,
                              void* d_out, int out_size)
{
    const int*   rows   = (const int*)d_in[0];
    const int*   cols   = (const int*)d_in[1];
    const float* vals   = (const float*)d_in[2];
    const float* embeds = (const float*)d_in[3];
    int n_edges = in_sizes[0];
    if (n_edges > N_EDGES_MAX) n_edges = N_EDGES_MAX;
    int n_nodes = out_size / D_FEAT;
    if (n_nodes > N_NODES_MAX) n_nodes = N_NODES_MAX;

    float* out = (float*)d_out;
    int n4 = out_size / 4;

    // 1) zero output + reset list heads
    {
        int threads = 256;
        int blocks = (n4 + threads - 1) / threads;
        if (blocks > 4096) blocks = 4096;
        init_kernel<<<blocks, threads>>>((float4*)out, n4, n_nodes);
    }

    // 2) build per-node linked lists
    {
        int threads = 256;
        int blocks = (n_edges + threads - 1) / threads;
        build_kernel<<<blocks, threads>>>(rows, cols, vals, n_edges);
    }

    // 3) gather-aggregate: 16 lanes per node, register accumulation
    {
        long long total = (long long)n_nodes * 16;
        int threads = 256;
        int blocks = (int)((total + threads - 1) / threads);
        aggregate_kernel<<<blocks, threads>>>(
            (const float4*)embeds, (float4*)out, n_nodes);
    }
}

// round 3
// speedup vs baseline: 1.1037x; 1.1037x over previous
#include <cuda_runtime.h>
#include <cuda_bf16.h>
#include <cstdint>

// GCN sparse aggregation: out[r,:] += vals[e] * embeds[cols[e],:]
// N=100000 nodes, E=1600000 edges, D=64, fp32.
//
// Round 3: counting-sort CSR (no full sort, no pointer chase):
//   1) init: zero out + zero per-row counts
//   2) hist: count[rows[e]]++
//   3) scan: exclusive prefix over counts (3 small kernels)
//   4) place: slot = cursor[r]++; edge[slot] = {col, val}  (8B packed)
//   5) aggregate: 16 lanes per node walk the row's contiguous slot range
//      with independent loads (full MLP), accumulate in regs, one float4
//      store per lane. No atomics on the fat 410MB path.

#define D_FEAT 64
#define NV 100000
#define NE 1600000
#define SCAN_BS 512
#define NB ((NV + SCAN_BS - 1) / SCAN_BS)   // 196

__device__ int  g_count[NV];
__device__ int  g_cursor[NV];
__device__ int  g_rowstart[NV + 1];
__device__ int  g_blocksum[NB];
__device__ int  g_blockoff[NB];
__device__ int2 g_edge[NE];                 // {col, val_bits}, grouped by row

__global__ void init_kernel(float4* __restrict__ out4, int n4, int n_nodes) {
    int i = blockIdx.x * blockDim.x + threadIdx.x;
    int s = gridDim.x * blockDim.x;
    for (int j = i; j < n4; j += s)
        out4[j] = make_float4(0.f, 0.f, 0.f, 0.f);
    for (int j = i; j < n_nodes; j += s)
        g_count[j] = 0;
}

__global__ void __launch_bounds__(256) hist_kernel(
    const int* __restrict__ rows, int n_edges)
{
    int e = blockIdx.x * blockDim.x + threadIdx.x;
    if (e < n_edges) atomicAdd(&g_count[rows[e]], 1);
}

// Block-level inclusive scan (Hillis-Steele in smem), emit per-element
// exclusive prefix + block totals.
__global__ void __launch_bounds__(SCAN_BS) scan1_kernel(int n_nodes) {
    __shared__ int sm[SCAN_BS];
    int g = blockIdx.x * SCAN_BS + threadIdx.x;
    int v = (g < n_nodes) ? g_count[g] : 0;
    sm[threadIdx.x] = v;
    __syncthreads();
    for (int off = 1; off < SCAN_BS; off <<= 1) {
        int t = (threadIdx.x >= off) ? sm[threadIdx.x - off] : 0;
        __syncthreads();
        sm[threadIdx.x] += t;
        __syncthreads();
    }
    if (g < n_nodes) g_cursor[g] = sm[threadIdx.x] - v;   // exclusive within block
    if (threadIdx.x == SCAN_BS - 1) g_blocksum[blockIdx.x] = sm[SCAN_BS - 1];
}

__global__ void __launch_bounds__(256) scan2_kernel() {
    __shared__ int sm[256];
    int tid = threadIdx.x;
    int v = (tid < NB) ? g_blocksum[tid] : 0;
    sm[tid] = v;
    __syncthreads();
    for (int off = 1; off < 256; off <<= 1) {
        int t = (tid >= off) ? sm[tid - off] : 0;
        __syncthreads();
        sm[tid] += t;
        __syncthreads();
    }
    if (tid < NB) g_blockoff[tid] = sm[tid] - v;          // exclusive block offsets
}

__global__ void __launch_bounds__(256) scan3_kernel(int n_nodes, int n_edges) {
    int g = blockIdx.x * blockDim.x + threadIdx.x;
    if (g < n_nodes) {
        int rs = g_cursor[g] + g_blockoff[g / SCAN_BS];
        g_rowstart[g] = rs;
        g_cursor[g] = rs;
    }
    if (g == 0) g_rowstart[n_nodes] = n_edges;
}

__global__ void __launch_bounds__(256) place_kernel(
    const int*   __restrict__ rows,
    const int*   __restrict__ cols,
    const float* __restrict__ vals,
    int n_edges)
{
    int e = blockIdx.x * blockDim.x + threadIdx.x;
    if (e >= n_edges) return;
    int r = rows[e];
    int pos = atomicAdd(&g_cursor[r], 1);
    g_edge[pos] = make_int2(cols[e], __float_as_int(vals[e]));
}

__global__ void __launch_bounds__(256) aggregate_kernel(
    const float4* __restrict__ embeds4,   // [NV, 16] float4
    float4*       __restrict__ out4,      // [NV, 16] float4
    int n_nodes)
{
    int t = blockIdx.x * blockDim.x + threadIdx.x;
    int node = t >> 4;
    int lane = t & 15;
    if (node >= n_nodes) return;

    int i   = g_rowstart[node];
    int end = g_rowstart[node + 1];

    float4 acc = make_float4(0.f, 0.f, 0.f, 0.f);

    // Unrolled by 2: independent loads -> MLP (no pointer chase).
    for (; i + 1 < end; i += 2) {
        int2 p0 = __ldg(&g_edge[i]);
        int2 p1 = __ldg(&g_edge[i + 1]);
        float4 x0 = __ldg(&embeds4[(size_t)p0.x * (D_FEAT / 4) + lane]);
        float4 x1 = __ldg(&embeds4[(size_t)p1.x * (D_FEAT / 4) + lane]);
        float v0 = __int_as_float(p0.y);
        float v1 = __int_as_float(p1.y);
        acc.x += v0 * x0.x; acc.y += v0 * x0.y;
        acc.z += v0 * x0.z; acc.w += v0 * x0.w;
        acc.x += v1 * x1.x; acc.y += v1 * x1.y;
        acc.z += v1 * x1.z; acc.w += v1 * x1.w;
    }
    if (i < end) {
        int2 p = __ldg(&g_edge[i]);
        float v = __int_as_float(p.y);
        float4 x = __ldg(&embeds4[(size_t)p.x * (D_FEAT / 4) + lane]);
        acc.x += v * x.x; acc.y += v * x.y;
        acc.z += v * x.z; acc.w += v * x.w;
    }
    out4[(size_t)node * (D_FEAT / 4) + lane] = acc;
}

extern "C" void kernel_launch(void* const* d_in, const int* in_sizes, int n_in,
                              void* d_out, int out_size)
{
    const int*   rows   = (const int*)d_in[0];
    const int*   cols   = (const int*)d_in[1];
    const float* vals   = (const float*)d_in[2];
    const float* embeds = (const float*)d_in[3];
    int n_edges = in_sizes[0];
    if (n_edges > NE) n_edges = NE;
    int n_nodes = out_size / D_FEAT;
    if (n_nodes > NV) n_nodes = NV;

    float* out = (float*)d_out;
    int n4 = out_size / 4;

    {   // 1) zero out + counts
        int threads = 256;
        int blocks = (n4 + threads - 1) / threads;
        if (blocks > 16384) blocks = 16384;
        init_kernel<<<blocks, threads>>>((float4*)out, n4, n_nodes);
    }
    {   // 2) histogram
        int threads = 256;
        int blocks = (n_edges + threads - 1) / threads;
        hist_kernel<<<blocks, threads>>>(rows, n_edges);
    }
    {   // 3) exclusive scan
        scan1_kernel<<<NB, SCAN_BS>>>(n_nodes);
        scan2_kernel<<<1, 256>>>();
        int threads = 256;
        int blocks = (n_nodes + threads - 1) / threads;
        scan3_kernel<<<blocks, threads>>>(n_nodes, n_edges);
    }
    {   // 4) place edges into CSR slots
        int threads = 256;
        int blocks = (n_edges + threads - 1) / threads;
        place_kernel<<<blocks, threads>>>(rows, cols, vals, n_edges);
    }
    {   // 5) aggregate
        long long total = (long long)n_nodes * 16;
        int threads = 256;
        int blocks = (int)((total + threads - 1) / threads);
        aggregate_kernel<<<blocks, threads>>>(
            (const float4*)embeds, (float4*)out, n_nodes);
    }
}

// round 4
// speedup vs baseline: 1.1041x; 1.0004x over previous
#include <cuda_runtime.h>
#include <cuda_bf16.h>
#include <cstdint>

// GCN sparse aggregation: out[r,:] += vals[e] * embeds[cols[e],:]
// N=100000 nodes, E=1600000 edges, D=64, fp32.
//
// Round 3: counting-sort CSR (no full sort, no pointer chase):
//   1) init: zero out + zero per-row counts
//   2) hist: count[rows[e]]++
//   3) scan: exclusive prefix over counts (3 small kernels)
//   4) place: slot = cursor[r]++; edge[slot] = {col, val}  (8B packed)
//   5) aggregate: 16 lanes per node walk the row's contiguous slot range
//      with independent loads (full MLP), accumulate in regs, one float4
//      store per lane. No atomics on the fat 410MB path.

#define D_FEAT 64
#define NV 100000
#define NE 1600000
#define SCAN_BS 512
#define NB ((NV + SCAN_BS - 1) / SCAN_BS)   // 196

__device__ int  g_count[NV];
__device__ int  g_cursor[NV];
__device__ int  g_rowstart[NV + 1];
__device__ int  g_blocksum[NB];
__device__ int  g_blockoff[NB];
__device__ int2 g_edge[NE];                 // {col, val_bits}, grouped by row

__global__ void init_kernel(float4* __restrict__ out4, int n4, int n_nodes) {
    int i = blockIdx.x * blockDim.x + threadIdx.x;
    int s = gridDim.x * blockDim.x;
    for (int j = i; j < n4; j += s)
        out4[j] = make_float4(0.f, 0.f, 0.f, 0.f);
    for (int j = i; j < n_nodes; j += s)
        g_count[j] = 0;
}

__global__ void __launch_bounds__(256) hist_kernel(
    const int* __restrict__ rows, int n_edges)
{
    int e = blockIdx.x * blockDim.x + threadIdx.x;
    if (e < n_edges) atomicAdd(&g_count[rows[e]], 1);
}

// Block-level inclusive scan (Hillis-Steele in smem), emit per-element
// exclusive prefix + block totals.
__global__ void __launch_bounds__(SCAN_BS) scan1_kernel(int n_nodes) {
    __shared__ int sm[SCAN_BS];
    int g = blockIdx.x * SCAN_BS + threadIdx.x;
    int v = (g < n_nodes) ? g_count[g] : 0;
    sm[threadIdx.x] = v;
    __syncthreads();
    for (int off = 1; off < SCAN_BS; off <<= 1) {
        int t = (threadIdx.x >= off) ? sm[threadIdx.x - off] : 0;
        __syncthreads();
        sm[threadIdx.x] += t;
        __syncthreads();
    }
    if (g < n_nodes) g_cursor[g] = sm[threadIdx.x] - v;   // exclusive within block
    if (threadIdx.x == SCAN_BS - 1) g_blocksum[blockIdx.x] = sm[SCAN_BS - 1];
}

__global__ void __launch_bounds__(256) scan2_kernel() {
    __shared__ int sm[256];
    int tid = threadIdx.x;
    int v = (tid < NB) ? g_blocksum[tid] : 0;
    sm[tid] = v;
    __syncthreads();
    for (int off = 1; off < 256; off <<= 1) {
        int t = (tid >= off) ? sm[tid - off] : 0;
        __syncthreads();
        sm[tid] += t;
        __syncthreads();
    }
    if (tid < NB) g_blockoff[tid] = sm[tid] - v;          // exclusive block offsets
}

__global__ void __launch_bounds__(256) scan3_kernel(int n_nodes, int n_edges) {
    int g = blockIdx.x * blockDim.x + threadIdx.x;
    if (g < n_nodes) {
        int rs = g_cursor[g] + g_blockoff[g / SCAN_BS];
        g_rowstart[g] = rs;
        g_cursor[g] = rs;
    }
    if (g == 0) g_rowstart[n_nodes] = n_edges;
}

__global__ void __launch_bounds__(256) place_kernel(
    const int*   __restrict__ rows,
    const int*   __restrict__ cols,
    const float* __restrict__ vals,
    int n_edges)
{
    int e = blockIdx.x * blockDim.x + threadIdx.x;
    if (e >= n_edges) return;
    int r = rows[e];
    int pos = atomicAdd(&g_cursor[r], 1);
    g_edge[pos] = make_int2(cols[e], __float_as_int(vals[e]));
}

__global__ void __launch_bounds__(256) aggregate_kernel(
    const float4* __restrict__ embeds4,   // [NV, 16] float4
    float4*       __restrict__ out4,      // [NV, 16] float4
    int n_nodes)
{
    int t = blockIdx.x * blockDim.x + threadIdx.x;
    int node = t >> 4;
    int lane = t & 15;
    if (node >= n_nodes) return;

    int i   = g_rowstart[node];
    int end = g_rowstart[node + 1];

    float4 acc = make_float4(0.f, 0.f, 0.f, 0.f);

    // Unrolled by 2: independent loads -> MLP (no pointer chase).
    for (; i + 1 < end; i += 2) {
        int2 p0 = __ldg(&g_edge[i]);
        int2 p1 = __ldg(&g_edge[i + 1]);
        float4 x0 = __ldg(&embeds4[(size_t)p0.x * (D_FEAT / 4) + lane]);
        float4 x1 = __ldg(&embeds4[(size_t)p1.x * (D_FEAT / 4) + lane]);
        float v0 = __int_as_float(p0.y);
        float v1 = __int_as_float(p1.y);
        acc.x += v0 * x0.x; acc.y += v0 * x0.y;
        acc.z += v0 * x0.z; acc.w += v0 * x0.w;
        acc.x += v1 * x1.x; acc.y += v1 * x1.y;
        acc.z += v1 * x1.z; acc.w += v1 * x1.w;
    }
    if (i < end) {
        int2 p = __ldg(&g_edge[i]);
        float v = __int_as_float(p.y);
        float4 x = __ldg(&embeds4[(size_t)p.x * (D_FEAT / 4) + lane]);
        acc.x += v * x.x; acc.y += v * x.y;
        acc.z += v * x.z; acc.w += v * x.w;
    }
    out4[(size_t)node * (D_FEAT / 4) + lane] = acc;
}

extern "C" void kernel_launch(void* const* d_in, const int* in_sizes, int n_in,
                              void* d_out, int out_size)
{
    const int*   rows   = (const int*)d_in[0];
    const int*   cols   = (const int*)d_in[1];
    const float* vals   = (const float*)d_in[2];
    const float* embeds = (const float*)d_in[3];
    int n_edges = in_sizes[0];
    if (n_edges > NE) n_edges = NE;
    int n_nodes = out_size / D_FEAT;
    if (n_nodes > NV) n_nodes = NV;

    float* out = (float*)d_out;
    int n4 = out_size / 4;

    {   // 1) zero out + counts
        int threads = 256;
        int blocks = (n4 + threads - 1) / threads;
        if (blocks > 16384) blocks = 16384;
        init_kernel<<<blocks, threads>>>((float4*)out, n4, n_nodes);
    }
    {   // 2) histogram
        int threads = 256;
        int blocks = (n_edges + threads - 1) / threads;
        hist_kernel<<<blocks, threads>>>(rows, n_edges);
    }
    {   // 3) exclusive scan
        scan1_kernel<<<NB, SCAN_BS>>>(n_nodes);
        scan2_kernel<<<1, 256>>>();
        int threads = 256;
        int blocks = (n_nodes + threads - 1) / threads;
        scan3_kernel<<<blocks, threads>>>(n_nodes, n_edges);
    }
    {   // 4) place edges into CSR slots
        int threads = 256;
        int blocks = (n_edges + threads - 1) / threads;
        place_kernel<<<blocks, threads>>>(rows, cols, vals, n_edges);
    }
    {   // 5) aggregate
        long long total = (long long)n_nodes * 16;
        int threads = 256;
        int blocks = (int)((total + threads - 1) / threads);
        aggregate_kernel<<<blocks, threads>>>(
            (const float4*)embeds, (float4*)out, n_nodes);
    }
}